// round 16
// baseline (speedup 1.0000x reference)
#include <cuda_runtime.h>
#include <cuda_bf16.h>
#include <math.h>
#include <stdint.h>

#define DDIM 256
#define HH   8
#define HD   32
#define EE   262144
#define NN   16384

// ---------------- device-global scratch (referenced ONLY in device code) ----
__device__ __nv_bfloat162 g_xb[NN * 128];     // hidden, bf16 k-pairs
__device__ __nv_bfloat162 g_wqb[128 * 768];   // Wqkv, paired along k
__device__ __nv_bfloat162 g_wob[128 * 256];   // Wo, paired along k
__device__ __nv_bfloat162 g_qb[NN * 128];     // q (scaled), bf16 pairs
__device__ __nv_bfloat162 g_kb[NN * 128];     // k, bf16 pairs
__device__ float g_attn[EE * HH];             // positional (CSR order)
__device__ __nv_bfloat162 g_hb[3][NN * 128];  // h0,h1,h2 planes (bf16x2)
__device__ __nv_bfloat162 g_gatherb[NN * 128];// combined gather, bf16 pairs
__device__ __align__(16) int g_cnt[NN];
__device__ __align__(16) int g_off[NN + 4];
__device__ __align__(16) int g_cursor[NN];
__device__ int   g_esrc[EE];
__device__ int   g_mask[NN];
__device__ int   g_gsel;

// ---------------- mma / ldmatrix helpers -------------------------------------
__device__ __forceinline__ void mma_bf16(float* d, const uint32_t* a, const uint32_t* b) {
    asm volatile(
        "mma.sync.aligned.m16n8k16.row.col.f32.bf16.bf16.f32 "
        "{%0,%1,%2,%3}, {%4,%5,%6,%7}, {%8,%9}, {%0,%1,%2,%3};"
        : "+f"(d[0]), "+f"(d[1]), "+f"(d[2]), "+f"(d[3])
        : "r"(a[0]), "r"(a[1]), "r"(a[2]), "r"(a[3]), "r"(b[0]), "r"(b[1]));
}

__device__ __forceinline__ void ldsm_x4(uint32_t* r, uint32_t addr) {
    asm volatile(
        "ldmatrix.sync.aligned.m8n8.x4.shared.b16 {%0,%1,%2,%3}, [%4];"
        : "=r"(r[0]), "=r"(r[1]), "=r"(r[2]), "=r"(r[3])
        : "r"(addr));
}

// ---------------- setup: converts + gamma select (main stream) --------------
__global__ void setup_kernel(const float* __restrict__ hidden,
                             const float* __restrict__ Wqkv,
                             const float* __restrict__ Wo,
                             const float* __restrict__ a,
                             const float* __restrict__ b,
                             const float* __restrict__ c) {
    int bid = blockIdx.x;
    int t = threadIdx.x;
    {
        long i = (long)bid * 256 + t;
        float2 v = *reinterpret_cast<const float2*>(&hidden[i * 2]);
        g_xb[i] = __floats2bfloat162_rn(v.x, v.y);
    }
    if (bid < 384) {
        int i = bid * 256 + t;
        int pk = i / 768, n = i - pk * 768;
        g_wqb[i] = __floats2bfloat162_rn(Wqkv[(long)(2 * pk) * 768 + n],
                                         Wqkv[(long)(2 * pk + 1) * 768 + n]);
    } else if (bid < 512) {
        int i = (bid - 384) * 256 + t;
        int pk = i >> 8, n = i & 255;
        g_wob[i] = __floats2bfloat162_rn(Wo[(long)(2 * pk) * 256 + n],
                                         Wo[(long)(2 * pk + 1) * 256 + n]);
    } else if (bid == 512) {
        __shared__ float s[3][8];
        float va = fabsf(a[t]), vb = fabsf(b[t]), vc = fabsf(c[t]);
#pragma unroll
        for (int o = 16; o > 0; o >>= 1) {
            va += __shfl_xor_sync(0xffffffffu, va, o);
            vb += __shfl_xor_sync(0xffffffffu, vb, o);
            vc += __shfl_xor_sync(0xffffffffu, vc, o);
        }
        if ((t & 31) == 0) { s[0][t >> 5] = va; s[1][t >> 5] = vb; s[2][t >> 5] = vc; }
        __syncthreads();
        if (t == 0) {
            float ta = 0, tb = 0, tc = 0;
            for (int i = 0; i < 8; i++) { ta += s[0][i]; tb += s[1][i]; tc += s[2][i]; }
            int idx = 0; float m = ta;
            if (tb > m) { m = tb; idx = 1; }
            if (tc > m) { m = tc; idx = 2; }
            g_gsel = idx;
        }
    }
}

// ---------------- prep (side stream head): mask + cnt clear -----------------
__global__ void prep_kernel(const float* __restrict__ am) {
    int n = blockIdx.x * blockDim.x + threadIdx.x;
    if (n < NN) {
        g_mask[n] = (am[n] >= 0.f) ? 1 : 0;
        g_cnt[n] = 0;
    }
}

// ---------------- QKV GEMM (bf16 m16n8k16, 128x128x32 tile, 512 thr) --------
__global__ __launch_bounds__(512) void gemm_qkv_kernel(const float* __restrict__ bias) {
    __shared__ uint32_t As[128][20];   // 2560 u32
    __shared__ uint32_t Bs[16][136];   // 2176 u32 (128 n + pad 8)

    const uint4* Xu4 = reinterpret_cast<const uint4*>(g_xb);    // [NN*32]
    const uint4* Wu4 = reinterpret_cast<const uint4*>(g_wqb);   // [128*192]

    int t = threadIdx.x;
    int lane = t & 31, w = t >> 5;        // 16 warps
    int wm = w & 3, wn = w >> 2;          // 4 M x 4 N
    int g = lane >> 2, tg = lane & 3;
    int row0 = blockIdx.y * 128;
    int col0 = blockIdx.x * 128;
    int mbase = wm * 32, nbase = wn * 32;

    uint32_t as_base = (uint32_t)__cvta_generic_to_shared(&As[0][0]);
    int lsel = lane >> 3, lrow = lane & 7;
    int lm_roff = (lsel & 1) * 8 + lrow;
    int lm_coff = (lsel >> 1) * 4;

    // A: 128 rows x 4 uint4 = 512 loads, 1/thread
    int aRow = t >> 2, aQ = t & 3;
    // B: 16 kpairs x 32 n-quads = 512 loads, 1/thread
    int bPk = t >> 5, bN4 = t & 31;

    float acc[2][4][4];
#pragma unroll
    for (int mi = 0; mi < 2; mi++)
#pragma unroll
        for (int ni = 0; ni < 4; ni++)
#pragma unroll
            for (int j = 0; j < 4; j++) acc[mi][ni][j] = 0.f;

    uint4 pa, pb;
    pa = Xu4[(long)(row0 + aRow) * 32 + aQ];
    pb = Wu4[(long)bPk * 192 + (col0 >> 2) + bN4];

#pragma unroll
    for (int k0 = 0; k0 < 256; k0 += 32) {
        *reinterpret_cast<uint4*>(&As[aRow][aQ * 4]) = pa;
        *reinterpret_cast<uint4*>(&Bs[bPk][bN4 * 4]) = pb;
        __syncthreads();

        if (k0 + 32 < 256) {
            int kn = k0 + 32;
            pa = Xu4[(long)(row0 + aRow) * 32 + (kn >> 3) + aQ];
            pb = Wu4[(long)((kn >> 1) + bPk) * 192 + (col0 >> 2) + bN4];
        }

#pragma unroll
        for (int kc = 0; kc < 2; kc++) {
            uint32_t a[2][4], b[4][2];
#pragma unroll
            for (int mi = 0; mi < 2; mi++) {
                int row = mbase + mi * 16 + lm_roff;
                int colp = kc * 8 + lm_coff;
                ldsm_x4(a[mi], as_base + (uint32_t)(row * 20 + colp) * 4u);
            }
#pragma unroll
            for (int ni = 0; ni < 4; ni++) {
                int nc = nbase + ni * 8 + g;
                b[ni][0] = Bs[kc * 8 + tg][nc];
                b[ni][1] = Bs[kc * 8 + tg + 4][nc];
            }
#pragma unroll
            for (int mi = 0; mi < 2; mi++)
#pragma unroll
                for (int ni = 0; ni < 4; ni++)
                    mma_bf16(acc[mi][ni], a[mi], b[ni]);
        }
        __syncthreads();
    }

    const float qscale = 0.17677669529663687f;
    const float einv   = 0.36787944117144233f;
#pragma unroll
    for (int mi = 0; mi < 2; mi++) {
#pragma unroll
        for (int ni = 0; ni < 4; ni++) {
            int r0 = row0 + mbase + mi * 16 + g;
            int c  = col0 + nbase + ni * 8 + tg * 2;
#pragma unroll
            for (int rr = 0; rr < 2; rr++) {
                int r = r0 + rr * 8;
                float v0 = acc[mi][ni][rr * 2 + 0] + bias[c];
                float v1 = acc[mi][ni][rr * 2 + 1] + bias[c + 1];
                if (c < 256) {
                    g_qb[(long)r * 128 + (c >> 1)] =
                        __floats2bfloat162_rn(v0 * qscale, v1 * qscale);
                } else if (c < 512) {
                    g_kb[(long)r * 128 + ((c - 256) >> 1)] =
                        __floats2bfloat162_rn(v0, v1);
                } else {
                    g_hb[0][(long)r * 128 + ((c - 512) >> 1)] =
                        __floats2bfloat162_rn(v0 * einv, v1 * einv);
                }
            }
        }
    }
}

// ---------------- fused out-GEMM (bf16, ldmatrix A) + resid + bo + LN -------
__global__ __launch_bounds__(512) void gemm_ln_kernel(const float* __restrict__ resid,
                                                      const float* __restrict__ p0,
                                                      const float* __restrict__ p1,
                                                      const float* __restrict__ p2,
                                                      float* __restrict__ out) {
    __shared__ uint32_t sbuf[5504];
    uint32_t (*As)[20]  = reinterpret_cast<uint32_t(*)[20]>(sbuf);
    uint32_t (*Bs)[264] = reinterpret_cast<uint32_t(*)[264]>(sbuf + 64 * 20);
    float* psum  = reinterpret_cast<float*>(sbuf);
    float* psq   = reinterpret_cast<float*>(sbuf + 2048);
    float* rmean = reinterpret_cast<float*>(sbuf + 4096);
    float* rstd  = reinterpret_cast<float*>(sbuf + 4160);

    const uint4* Gu4 = reinterpret_cast<const uint4*>(g_gatherb);
    const uint4* Wu4 = reinterpret_cast<const uint4*>(g_wob);

    int sel = g_gsel;
    const float* gamma = (sel == 0) ? p0 : ((sel == 1) ? p1 : p2);
    const float* bo    = (sel == 0) ? p1 : p0;
    const float* beta  = (sel == 2) ? p1 : p2;

    int t = threadIdx.x;
    int lane = t & 31, w = t >> 5;
    int wm = w & 1, wn = w >> 1;
    int g = lane >> 2, tg = lane & 3;
    int row0 = blockIdx.x * 64;
    int mbase = wm * 32, nbase = wn * 32;

    uint32_t as_base = (uint32_t)__cvta_generic_to_shared(&sbuf[0]);
    int lsel = lane >> 3, lrow = lane & 7;
    int lm_roff = (lsel & 1) * 8 + lrow;
    int lm_coff = (lsel >> 1) * 4;

    int aRow = t >> 2, aQ = t & 3;
    int bPk[2], bN4[2];
#pragma unroll
    for (int i = 0; i < 2; i++) { int idx = t + i * 512; bN4[i] = idx & 63; bPk[i] = idx >> 6; }

    float acc[2][4][4];
#pragma unroll
    for (int mi = 0; mi < 2; mi++)
#pragma unroll
        for (int ni = 0; ni < 4; ni++)
#pragma unroll
            for (int j = 0; j < 4; j++) acc[mi][ni][j] = 0.f;

    uint4 pa, pb[2];
    if (t < 256) pa = Gu4[(long)(row0 + aRow) * 32 + aQ];
#pragma unroll
    for (int i = 0; i < 2; i++)
        pb[i] = Wu4[(long)bPk[i] * 64 + bN4[i]];

#pragma unroll
    for (int k0 = 0; k0 < 256; k0 += 32) {
        if (t < 256)
            *reinterpret_cast<uint4*>(&As[aRow][aQ * 4]) = pa;
#pragma unroll
        for (int i = 0; i < 2; i++)
            *reinterpret_cast<uint4*>(&Bs[bPk[i]][bN4[i] * 4]) = pb[i];
        __syncthreads();

        if (k0 + 32 < 256) {
            int kn = k0 + 32;
            if (t < 256) pa = Gu4[(long)(row0 + aRow) * 32 + (kn >> 3) + aQ];
#pragma unroll
            for (int i = 0; i < 2; i++)
                pb[i] = Wu4[(long)((kn >> 1) + bPk[i]) * 64 + bN4[i]];
        }

#pragma unroll
        for (int kc = 0; kc < 2; kc++) {
            uint32_t a[2][4], b[4][2];
#pragma unroll
            for (int mi = 0; mi < 2; mi++) {
                int row = mbase + mi * 16 + lm_roff;
                int colp = kc * 8 + lm_coff;
                ldsm_x4(a[mi], as_base + (uint32_t)(row * 20 + colp) * 4u);
            }
#pragma unroll
            for (int ni = 0; ni < 4; ni++) {
                int nc = nbase + ni * 8 + g;
                b[ni][0] = Bs[kc * 8 + tg][nc];
                b[ni][1] = Bs[kc * 8 + tg + 4][nc];
            }
#pragma unroll
            for (int mi = 0; mi < 2; mi++)
#pragma unroll
                for (int ni = 0; ni < 4; ni++)
                    mma_bf16(acc[mi][ni], a[mi], b[ni]);
        }
        __syncthreads();
    }

    int slot = wn * 4 + tg;
#pragma unroll
    for (int mi = 0; mi < 2; mi++) {
#pragma unroll
        for (int rr = 0; rr < 2; rr++) {
            int rl = mbase + mi * 16 + g + rr * 8;
            int rg = row0 + rl;
            float s = 0.f, q = 0.f;
#pragma unroll
            for (int ni = 0; ni < 4; ni++) {
                int c = nbase + ni * 8 + tg * 2;
                const float2 rv = *reinterpret_cast<const float2*>(
                    &resid[(long)rg * DDIM + c]);
                float v0 = acc[mi][ni][rr * 2 + 0] + rv.x + bo[c];
                float v1 = acc[mi][ni][rr * 2 + 1] + rv.y + bo[c + 1];
                acc[mi][ni][rr * 2 + 0] = v0;
                acc[mi][ni][rr * 2 + 1] = v1;
                s += v0 + v1;
                q += v0 * v0 + v1 * v1;
            }
            psum[rl * 32 + slot] = s;
            psq[rl * 32 + slot]  = q;
        }
    }
    __syncthreads();

#pragma unroll
    for (int j = 0; j < 4; j++) {
        int r = w * 4 + j;
        float sv = psum[r * 32 + lane];
        float qv = psq[r * 32 + lane];
#pragma unroll
        for (int o = 16; o > 0; o >>= 1) {
            sv += __shfl_xor_sync(0xffffffffu, sv, o);
            qv += __shfl_xor_sync(0xffffffffu, qv, o);
        }
        if (lane == 0) {
            float mean = sv * (1.0f / 256.0f);
            float var = qv * (1.0f / 256.0f) - mean * mean;
            rmean[r] = mean;
            rstd[r] = rsqrtf(var + 1e-12f);
        }
    }
    __syncthreads();

#pragma unroll
    for (int mi = 0; mi < 2; mi++) {
#pragma unroll
        for (int rr = 0; rr < 2; rr++) {
            int rl = mbase + mi * 16 + g + rr * 8;
            int rg = row0 + rl;
            float mean = rmean[rl], istd = rstd[rl];
#pragma unroll
            for (int ni = 0; ni < 4; ni++) {
                int c = nbase + ni * 8 + tg * 2;
                float v0 = (acc[mi][ni][rr * 2 + 0] - mean) * istd * gamma[c] + beta[c];
                float v1 = (acc[mi][ni][rr * 2 + 1] - mean) * istd * gamma[c + 1] + beta[c + 1];
                *reinterpret_cast<float2*>(&out[(long)rg * DDIM + c]) =
                    make_float2(v0, v1);
            }
        }
    }
}

// ---------------- CSR build --------------------------------------------------
__global__ void hist_kernel(const int* __restrict__ dst) {
    int e = blockIdx.x * blockDim.x + threadIdx.x;
    if (e < EE) atomicAdd(&g_cnt[dst[e]], 1);
}

__global__ void scan_kernel() {
    int t = threadIdx.x;
    int lane = t & 31, w = t >> 5;
    int local[16];
    const int4* cp = reinterpret_cast<const int4*>(g_cnt);
#pragma unroll
    for (int i = 0; i < 4; i++) {
        int4 v = cp[t * 4 + i];
        local[i * 4 + 0] = v.x; local[i * 4 + 1] = v.y;
        local[i * 4 + 2] = v.z; local[i * 4 + 3] = v.w;
    }
    int mine = 0;
#pragma unroll
    for (int j = 0; j < 16; j++) mine += local[j];

    int inc = mine;
#pragma unroll
    for (int o = 1; o < 32; o <<= 1) {
        int v = __shfl_up_sync(0xffffffffu, inc, o);
        if (lane >= o) inc += v;
    }
    __shared__ int ws[32];
    if (lane == 31) ws[w] = inc;
    __syncthreads();
    if (w == 0) {
        int v = ws[lane];
#pragma unroll
        for (int o = 1; o < 32; o <<= 1) {
            int u = __shfl_up_sync(0xffffffffu, v, o);
            if (lane >= o) v += u;
        }
        ws[lane] = v;
    }
    __syncthreads();
    int base = ((w > 0) ? ws[w - 1] : 0) + inc - mine;

    int vals[16];
#pragma unroll
    for (int j = 0; j < 16; j++) { vals[j] = base; base += local[j]; }
    int4* op = reinterpret_cast<int4*>(g_off);
    int4* up = reinterpret_cast<int4*>(g_cursor);
#pragma unroll
    for (int i = 0; i < 4; i++) {
        int4 v = make_int4(vals[i * 4], vals[i * 4 + 1], vals[i * 4 + 2], vals[i * 4 + 3]);
        op[t * 4 + i] = v;
        up[t * 4 + i] = v;
    }
    if (t == 1023) g_off[NN] = base;
}

__global__ void scatter_kernel(const int* __restrict__ src,
                               const int* __restrict__ dst) {
    int e = blockIdx.x * blockDim.x + threadIdx.x;
    if (e < EE) {
        int p = atomicAdd(&g_cursor[dst[e]], 1);
        g_esrc[p] = src[e];
    }
}

// ---------------- edge softmax: warp=head, 8 lanes/edge, bf16 q/k -----------
__global__ void edge_softmax_kernel() {
    int node = blockIdx.x;
    int w = threadIdx.x >> 5;
    int lane = threadIdx.x & 31;
    int start = g_off[node], end = g_off[node + 1];
    if (start == end) return;
    int dm = g_mask[node];
    int grp = lane >> 3;
    int sub = lane & 7;

    const uint2 qu = *reinterpret_cast<const uint2*>(
        &g_qb[(long)node * 128 + w * 16 + sub * 2]);
    float2 q01 = __bfloat1622float2(*reinterpret_cast<const __nv_bfloat162*>(&qu.x));
    float2 q23 = __bfloat1622float2(*reinterpret_cast<const __nv_bfloat162*>(&qu.y));

    float mx = -1e30f;
    for (int p0 = start; p0 < end; p0 += 4) {
        int p = p0 + grp;
        bool valid = (p < end);
        int s = valid ? g_esrc[p] : 0;
        uint2 ku = valid ? *reinterpret_cast<const uint2*>(
                               &g_kb[(long)s * 128 + w * 16 + sub * 2])
                         : make_uint2(0u, 0u);
        float2 k01 = __bfloat1622float2(*reinterpret_cast<const __nv_bfloat162*>(&ku.x));
        float2 k23 = __bfloat1622float2(*reinterpret_cast<const __nv_bfloat162*>(&ku.y));
        float d = q01.x * k01.x + q01.y * k01.y + q23.x * k23.x + q23.y * k23.y;
        d += __shfl_xor_sync(0xffffffffu, d, 1);
        d += __shfl_xor_sync(0xffffffffu, d, 2);
        d += __shfl_xor_sync(0xffffffffu, d, 4);
        if (valid) {
            int m = dm & g_mask[s];
            float sc = m ? d : -10000.0f;
            mx = fmaxf(mx, sc);
            if (sub == 0) g_attn[(long)p * HH + w] = sc;
        }
    }
    mx = fmaxf(mx, __shfl_xor_sync(0xffffffffu, mx, 8));
    mx = fmaxf(mx, __shfl_xor_sync(0xffffffffu, mx, 16));
    mx = fmaxf(mx, __shfl_xor_sync(0xffffffffu, mx, 1));
    mx = fmaxf(mx, __shfl_xor_sync(0xffffffffu, mx, 2));
    mx = fmaxf(mx, __shfl_xor_sync(0xffffffffu, mx, 4));
    __syncwarp();

    float den = 0.f;
    for (int p = start + lane; p < end; p += 32) {
        den += expf(g_attn[(long)p * HH + w] - mx);
    }
#pragma unroll
    for (int o = 16; o > 0; o >>= 1) den += __shfl_xor_sync(0xffffffffu, den, o);
    float inv = 1.0f / den;
    __syncwarp();
    for (int p = start + lane; p < end; p += 32) {
        g_attn[(long)p * HH + w] = expf(g_attn[(long)p * HH + w] - mx) * inv;
    }
}

// ---------------- diffusion: h[ii+1] = A_hat @ h[ii] -------------------------
__global__ void diffuse_kernel(int ii, int last) {
    const __nv_bfloat162* __restrict__ hp = g_hb[ii];
    __nv_bfloat162* __restrict__ hn = g_hb[last ? 0 : (ii + 1)];
    int node = blockIdx.x;
    int t = threadIdx.x;
    int hh = t >> 4;
    int start = g_off[node], end = g_off[node + 1];
    float ax = 0.f, ay = 0.f;
    int p = start;
    for (; p + 8 <= end; p += 8) {
        int s[8]; float a[8]; float2 v[8];
#pragma unroll
        for (int i = 0; i < 8; i++) s[i] = g_esrc[p + i];
#pragma unroll
        for (int i = 0; i < 8; i++) a[i] = g_attn[(long)(p + i) * HH + hh];
#pragma unroll
        for (int i = 0; i < 8; i++) v[i] = __bfloat1622float2(hp[(long)s[i] * 128 + t]);
#pragma unroll
        for (int i = 0; i < 8; i++) { ax += a[i] * v[i].x; ay += a[i] * v[i].y; }
    }
    for (; p + 4 <= end; p += 4) {
        int s[4]; float a[4]; float2 v[4];
#pragma unroll
        for (int i = 0; i < 4; i++) s[i] = g_esrc[p + i];
#pragma unroll
        for (int i = 0; i < 4; i++) a[i] = g_attn[(long)(p + i) * HH + hh];
#pragma unroll
        for (int i = 0; i < 4; i++) v[i] = __bfloat1622float2(hp[(long)s[i] * 128 + t]);
#pragma unroll
        for (int i = 0; i < 4; i++) { ax += a[i] * v[i].x; ay += a[i] * v[i].y; }
    }
    for (; p < end; p++) {
        int s = g_esrc[p];
        float a = g_attn[(long)p * HH + hh];
        float2 v = __bfloat1622float2(hp[(long)s * 128 + t]);
        ax += a * v.x;
        ay += a * v.y;
    }
    if (!last) {
        hn[(long)node * 128 + t] = __floats2bfloat162_rn(ax, ay);
    } else {
        float2 h0v = __bfloat1622float2(g_hb[0][(long)node * 128 + t]);
        float2 h1v = __bfloat1622float2(g_hb[1][(long)node * 128 + t]);
        float2 h2v = __bfloat1622float2(g_hb[2][(long)node * 128 + t]);
        const float w3 = 1.0f / 6.0f;
        float gx = h0v.x + h1v.x + 0.5f * h2v.x + w3 * ax;
        float gy = h0v.y + h1v.y + 0.5f * h2v.y + w3 * ay;
        g_gatherb[(long)node * 128 + t] = __floats2bfloat162_rn(gx, gy);
    }
}

// ---------------- launch ------------------------------------------------------
extern "C" void kernel_launch(void* const* d_in, const int* in_sizes, int n_in,
                              void* d_out, int out_size) {
    const void* p4194304 = 0; const void* p16384 = 0;
    const void* p262144a = 0; const void* p262144b = 0;
    const void* p196608 = 0;  const void* p768 = 0; const void* p65536 = 0;
    const void* p256a = 0; const void* p256b = 0; const void* p256c = 0;
    for (int i = 0; i < n_in; i++) {
        int sz = in_sizes[i]; const void* p = d_in[i];
        if      (sz == 4194304) p4194304 = p;
        else if (sz == 16384)   p16384 = p;
        else if (sz == 262144)  { if (!p262144a) p262144a = p; else p262144b = p; }
        else if (sz == 196608)  p196608 = p;
        else if (sz == 768)     p768 = p;
        else if (sz == 65536)   p65536 = p;
        else if (sz == 256)     { if (!p256a) p256a = p; else if (!p256b) p256b = p; else p256c = p; }
    }
    const float* hidden = (const float*)p4194304;
    const float* amask  = (const float*)p16384;
    const int*   src    = (const int*)p262144a;
    const int*   dst    = (const int*)p262144b;
    const float* Wqkv   = (const float*)p196608;
    const float* bqkv   = (const float*)p768;
    const float* Wo     = (const float*)p65536;
    const float* v256_0 = (const float*)p256a;
    const float* v256_1 = (const float*)p256b;
    const float* v256_2 = (const float*)p256c;

    float* out = (float*)d_out;

    static cudaStream_t s2 = nullptr;
    static cudaEvent_t ev_fork = nullptr, ev_join = nullptr;
    if (!s2) {
        cudaStreamCreateWithFlags(&s2, cudaStreamNonBlocking);
        cudaEventCreateWithFlags(&ev_fork, cudaEventDisableTiming);
        cudaEventCreateWithFlags(&ev_join, cudaEventDisableTiming);
    }

    cudaEventRecord(ev_fork, 0);
    cudaStreamWaitEvent(s2, ev_fork, 0);

    prep_kernel<<<NN / 256, 256, 0, s2>>>(amask);
    hist_kernel<<<EE / 256, 256, 0, s2>>>(dst);
    scan_kernel<<<1, 1024, 0, s2>>>();
    scatter_kernel<<<EE / 256, 256, 0, s2>>>(src, dst);
    cudaEventRecord(ev_join, s2);

    setup_kernel<<<8192, 256>>>(hidden, Wqkv, Wo, v256_0, v256_1, v256_2);
    {
        dim3 grid(768 / 128, NN / 128);
        gemm_qkv_kernel<<<grid, 512>>>(bqkv);
    }

    cudaStreamWaitEvent(0, ev_join, 0);

    edge_softmax_kernel<<<NN, 256>>>();

    diffuse_kernel<<<NN, 128>>>(0, 0);
    diffuse_kernel<<<NN, 128>>>(1, 0);
    diffuse_kernel<<<NN, 128>>>(2, 1);

    gemm_ln_kernel<<<NN / 64, 512>>>(hidden, v256_0, v256_1, v256_2, out);
}

// round 17
// speedup vs baseline: 1.1001x; 1.1001x over previous
#include <cuda_runtime.h>
#include <cuda_bf16.h>
#include <math.h>
#include <stdint.h>

#define DDIM 256
#define HH   8
#define HD   32
#define EE   262144
#define NN   16384

// ---------------- device-global scratch (referenced ONLY in device code) ----
__device__ __nv_bfloat162 g_xb[NN * 128];     // hidden, bf16 k-pairs
__device__ __nv_bfloat162 g_wqb[128 * 768];   // Wqkv, paired along k
__device__ __nv_bfloat162 g_wob[128 * 256];   // Wo, paired along k
__device__ __nv_bfloat162 g_qb[NN * 128];     // q (scaled), bf16 pairs
__device__ __nv_bfloat162 g_kb[NN * 128];     // k, bf16 pairs
__device__ float g_attn[HH][EE];              // attn planes, [head][CSR pos]
__device__ __nv_bfloat162 g_hb[3][NN * 128];  // h0,h1,h2 planes (bf16x2)
__device__ __nv_bfloat162 g_gatherb[NN * 128];// combined gather, bf16 pairs
__device__ __align__(16) int g_cnt[NN];
__device__ __align__(16) int g_off[NN + 4];
__device__ __align__(16) int g_cursor[NN];
__device__ int   g_esrc[EE];
__device__ int   g_mask[NN];
__device__ int   g_gsel;

// ---------------- mma / ldmatrix helpers -------------------------------------
__device__ __forceinline__ void mma_bf16(float* d, const uint32_t* a, const uint32_t* b) {
    asm volatile(
        "mma.sync.aligned.m16n8k16.row.col.f32.bf16.bf16.f32 "
        "{%0,%1,%2,%3}, {%4,%5,%6,%7}, {%8,%9}, {%0,%1,%2,%3};"
        : "+f"(d[0]), "+f"(d[1]), "+f"(d[2]), "+f"(d[3])
        : "r"(a[0]), "r"(a[1]), "r"(a[2]), "r"(a[3]), "r"(b[0]), "r"(b[1]));
}

__device__ __forceinline__ void ldsm_x4(uint32_t* r, uint32_t addr) {
    asm volatile(
        "ldmatrix.sync.aligned.m8n8.x4.shared.b16 {%0,%1,%2,%3}, [%4];"
        : "=r"(r[0]), "=r"(r[1]), "=r"(r[2]), "=r"(r[3])
        : "r"(addr));
}

// ---------------- setup: converts + gamma select (main stream) --------------
__global__ void setup_kernel(const float* __restrict__ hidden,
                             const float* __restrict__ Wqkv,
                             const float* __restrict__ Wo,
                             const float* __restrict__ a,
                             const float* __restrict__ b,
                             const float* __restrict__ c) {
    int bid = blockIdx.x;
    int t = threadIdx.x;
    {
        long i = (long)bid * 256 + t;
        float2 v = *reinterpret_cast<const float2*>(&hidden[i * 2]);
        g_xb[i] = __floats2bfloat162_rn(v.x, v.y);
    }
    if (bid < 384) {
        int i = bid * 256 + t;
        int pk = i / 768, n = i - pk * 768;
        g_wqb[i] = __floats2bfloat162_rn(Wqkv[(long)(2 * pk) * 768 + n],
                                         Wqkv[(long)(2 * pk + 1) * 768 + n]);
    } else if (bid < 512) {
        int i = (bid - 384) * 256 + t;
        int pk = i >> 8, n = i & 255;
        g_wob[i] = __floats2bfloat162_rn(Wo[(long)(2 * pk) * 256 + n],
                                         Wo[(long)(2 * pk + 1) * 256 + n]);
    } else if (bid == 512) {
        __shared__ float s[3][8];
        float va = fabsf(a[t]), vb = fabsf(b[t]), vc = fabsf(c[t]);
#pragma unroll
        for (int o = 16; o > 0; o >>= 1) {
            va += __shfl_xor_sync(0xffffffffu, va, o);
            vb += __shfl_xor_sync(0xffffffffu, vb, o);
            vc += __shfl_xor_sync(0xffffffffu, vc, o);
        }
        if ((t & 31) == 0) { s[0][t >> 5] = va; s[1][t >> 5] = vb; s[2][t >> 5] = vc; }
        __syncthreads();
        if (t == 0) {
            float ta = 0, tb = 0, tc = 0;
            for (int i = 0; i < 8; i++) { ta += s[0][i]; tb += s[1][i]; tc += s[2][i]; }
            int idx = 0; float m = ta;
            if (tb > m) { m = tb; idx = 1; }
            if (tc > m) { m = tc; idx = 2; }
            g_gsel = idx;
        }
    }
}

// ---------------- prep (side stream head): mask + cnt clear -----------------
__global__ void prep_kernel(const float* __restrict__ am) {
    int n = blockIdx.x * blockDim.x + threadIdx.x;
    if (n < NN) {
        g_mask[n] = (am[n] >= 0.f) ? 1 : 0;
        g_cnt[n] = 0;
    }
}

// ---------------- QKV GEMM (bf16 m16n8k16, 128x64x32 tile, ldmatrix A) ------
__global__ __launch_bounds__(256) void gemm_qkv_kernel(const float* __restrict__ bias) {
    __shared__ uint32_t As[128][20];
    __shared__ uint32_t Bs[16][72];

    const uint4* Xu4 = reinterpret_cast<const uint4*>(g_xb);
    const uint4* Wu4 = reinterpret_cast<const uint4*>(g_wqb);

    int t = threadIdx.x;
    int lane = t & 31, w = t >> 5;
    int wm = w & 3, wn = w >> 2;
    int g = lane >> 2, tg = lane & 3;
    int row0 = blockIdx.y * 128;
    int col0 = blockIdx.x * 64;
    int mbase = wm * 32, nbase = wn * 32;

    uint32_t as_base = (uint32_t)__cvta_generic_to_shared(&As[0][0]);
    int lsel = lane >> 3, lrow = lane & 7;
    int lm_roff = (lsel & 1) * 8 + lrow;
    int lm_coff = (lsel >> 1) * 4;

    int aRow[2], aQ[2];
#pragma unroll
    for (int i = 0; i < 2; i++) { int idx = t + i * 256; aRow[i] = idx >> 2; aQ[i] = idx & 3; }
    int bN4 = t & 15, bPk = t >> 4;

    float acc[2][4][4];
#pragma unroll
    for (int mi = 0; mi < 2; mi++)
#pragma unroll
        for (int ni = 0; ni < 4; ni++)
#pragma unroll
            for (int j = 0; j < 4; j++) acc[mi][ni][j] = 0.f;

    uint4 pa[2], pb;
#pragma unroll
    for (int i = 0; i < 2; i++)
        pa[i] = Xu4[(long)(row0 + aRow[i]) * 32 + aQ[i]];
    pb = Wu4[(long)bPk * 192 + (col0 >> 2) + bN4];

#pragma unroll
    for (int k0 = 0; k0 < 256; k0 += 32) {
#pragma unroll
        for (int i = 0; i < 2; i++)
            *reinterpret_cast<uint4*>(&As[aRow[i]][aQ[i] * 4]) = pa[i];
        *reinterpret_cast<uint4*>(&Bs[bPk][bN4 * 4]) = pb;
        __syncthreads();

        if (k0 + 32 < 256) {
            int kn = k0 + 32;
#pragma unroll
            for (int i = 0; i < 2; i++)
                pa[i] = Xu4[(long)(row0 + aRow[i]) * 32 + (kn >> 3) + aQ[i]];
            pb = Wu4[(long)((kn >> 1) + bPk) * 192 + (col0 >> 2) + bN4];
        }

#pragma unroll
        for (int kc = 0; kc < 2; kc++) {
            uint32_t a[2][4], b[4][2];
#pragma unroll
            for (int mi = 0; mi < 2; mi++) {
                int row = mbase + mi * 16 + lm_roff;
                int colp = kc * 8 + lm_coff;
                ldsm_x4(a[mi], as_base + (uint32_t)(row * 20 + colp) * 4u);
            }
#pragma unroll
            for (int ni = 0; ni < 4; ni++) {
                int nc = nbase + ni * 8 + g;
                b[ni][0] = Bs[kc * 8 + tg][nc];
                b[ni][1] = Bs[kc * 8 + tg + 4][nc];
            }
#pragma unroll
            for (int mi = 0; mi < 2; mi++)
#pragma unroll
                for (int ni = 0; ni < 4; ni++)
                    mma_bf16(acc[mi][ni], a[mi], b[ni]);
        }
        __syncthreads();
    }

    const float qscale = 0.17677669529663687f;
    const float einv   = 0.36787944117144233f;
#pragma unroll
    for (int mi = 0; mi < 2; mi++) {
#pragma unroll
        for (int ni = 0; ni < 4; ni++) {
            int r0 = row0 + mbase + mi * 16 + g;
            int c  = col0 + nbase + ni * 8 + tg * 2;
#pragma unroll
            for (int rr = 0; rr < 2; rr++) {
                int r = r0 + rr * 8;
                float v0 = acc[mi][ni][rr * 2 + 0] + bias[c];
                float v1 = acc[mi][ni][rr * 2 + 1] + bias[c + 1];
                if (c < 256) {
                    g_qb[(long)r * 128 + (c >> 1)] =
                        __floats2bfloat162_rn(v0 * qscale, v1 * qscale);
                } else if (c < 512) {
                    g_kb[(long)r * 128 + ((c - 256) >> 1)] =
                        __floats2bfloat162_rn(v0, v1);
                } else {
                    g_hb[0][(long)r * 128 + ((c - 512) >> 1)] =
                        __floats2bfloat162_rn(v0 * einv, v1 * einv);
                }
            }
        }
    }
}

// ---------------- fused out-GEMM (bf16, ldmatrix A) + resid + bo + LN -------
__global__ __launch_bounds__(512) void gemm_ln_kernel(const float* __restrict__ resid,
                                                      const float* __restrict__ p0,
                                                      const float* __restrict__ p1,
                                                      const float* __restrict__ p2,
                                                      float* __restrict__ out) {
    __shared__ uint32_t sbuf[5504];
    uint32_t (*As)[20]  = reinterpret_cast<uint32_t(*)[20]>(sbuf);
    uint32_t (*Bs)[264] = reinterpret_cast<uint32_t(*)[264]>(sbuf + 64 * 20);
    float* psum  = reinterpret_cast<float*>(sbuf);
    float* psq   = reinterpret_cast<float*>(sbuf + 2048);
    float* rmean = reinterpret_cast<float*>(sbuf + 4096);
    float* rstd  = reinterpret_cast<float*>(sbuf + 4160);

    const uint4* Gu4 = reinterpret_cast<const uint4*>(g_gatherb);
    const uint4* Wu4 = reinterpret_cast<const uint4*>(g_wob);

    int sel = g_gsel;
    const float* gamma = (sel == 0) ? p0 : ((sel == 1) ? p1 : p2);
    const float* bo    = (sel == 0) ? p1 : p0;
    const float* beta  = (sel == 2) ? p1 : p2;

    int t = threadIdx.x;
    int lane = t & 31, w = t >> 5;
    int wm = w & 1, wn = w >> 1;
    int g = lane >> 2, tg = lane & 3;
    int row0 = blockIdx.x * 64;
    int mbase = wm * 32, nbase = wn * 32;

    uint32_t as_base = (uint32_t)__cvta_generic_to_shared(&sbuf[0]);
    int lsel = lane >> 3, lrow = lane & 7;
    int lm_roff = (lsel & 1) * 8 + lrow;
    int lm_coff = (lsel >> 1) * 4;

    int aRow = t >> 2, aQ = t & 3;
    int bPk[2], bN4[2];
#pragma unroll
    for (int i = 0; i < 2; i++) { int idx = t + i * 512; bN4[i] = idx & 63; bPk[i] = idx >> 6; }

    float acc[2][4][4];
#pragma unroll
    for (int mi = 0; mi < 2; mi++)
#pragma unroll
        for (int ni = 0; ni < 4; ni++)
#pragma unroll
            for (int j = 0; j < 4; j++) acc[mi][ni][j] = 0.f;

    uint4 pa, pb[2];
    if (t < 256) pa = Gu4[(long)(row0 + aRow) * 32 + aQ];
#pragma unroll
    for (int i = 0; i < 2; i++)
        pb[i] = Wu4[(long)bPk[i] * 64 + bN4[i]];

#pragma unroll
    for (int k0 = 0; k0 < 256; k0 += 32) {
        if (t < 256)
            *reinterpret_cast<uint4*>(&As[aRow][aQ * 4]) = pa;
#pragma unroll
        for (int i = 0; i < 2; i++)
            *reinterpret_cast<uint4*>(&Bs[bPk[i]][bN4[i] * 4]) = pb[i];
        __syncthreads();

        if (k0 + 32 < 256) {
            int kn = k0 + 32;
            if (t < 256) pa = Gu4[(long)(row0 + aRow) * 32 + (kn >> 3) + aQ];
#pragma unroll
            for (int i = 0; i < 2; i++)
                pb[i] = Wu4[(long)((kn >> 1) + bPk[i]) * 64 + bN4[i]];
        }

#pragma unroll
        for (int kc = 0; kc < 2; kc++) {
            uint32_t a[2][4], b[4][2];
#pragma unroll
            for (int mi = 0; mi < 2; mi++) {
                int row = mbase + mi * 16 + lm_roff;
                int colp = kc * 8 + lm_coff;
                ldsm_x4(a[mi], as_base + (uint32_t)(row * 20 + colp) * 4u);
            }
#pragma unroll
            for (int ni = 0; ni < 4; ni++) {
                int nc = nbase + ni * 8 + g;
                b[ni][0] = Bs[kc * 8 + tg][nc];
                b[ni][1] = Bs[kc * 8 + tg + 4][nc];
            }
#pragma unroll
            for (int mi = 0; mi < 2; mi++)
#pragma unroll
                for (int ni = 0; ni < 4; ni++)
                    mma_bf16(acc[mi][ni], a[mi], b[ni]);
        }
        __syncthreads();
    }

    int slot = wn * 4 + tg;
#pragma unroll
    for (int mi = 0; mi < 2; mi++) {
#pragma unroll
        for (int rr = 0; rr < 2; rr++) {
            int rl = mbase + mi * 16 + g + rr * 8;
            int rg = row0 + rl;
            float s = 0.f, q = 0.f;
#pragma unroll
            for (int ni = 0; ni < 4; ni++) {
                int c = nbase + ni * 8 + tg * 2;
                const float2 rv = *reinterpret_cast<const float2*>(
                    &resid[(long)rg * DDIM + c]);
                float v0 = acc[mi][ni][rr * 2 + 0] + rv.x + bo[c];
                float v1 = acc[mi][ni][rr * 2 + 1] + rv.y + bo[c + 1];
                acc[mi][ni][rr * 2 + 0] = v0;
                acc[mi][ni][rr * 2 + 1] = v1;
                s += v0 + v1;
                q += v0 * v0 + v1 * v1;
            }
            psum[rl * 32 + slot] = s;
            psq[rl * 32 + slot]  = q;
        }
    }
    __syncthreads();

#pragma unroll
    for (int j = 0; j < 4; j++) {
        int r = w * 4 + j;
        float sv = psum[r * 32 + lane];
        float qv = psq[r * 32 + lane];
#pragma unroll
        for (int o = 16; o > 0; o >>= 1) {
            sv += __shfl_xor_sync(0xffffffffu, sv, o);
            qv += __shfl_xor_sync(0xffffffffu, qv, o);
        }
        if (lane == 0) {
            float mean = sv * (1.0f / 256.0f);
            float var = qv * (1.0f / 256.0f) - mean * mean;
            rmean[r] = mean;
            rstd[r] = rsqrtf(var + 1e-12f);
        }
    }
    __syncthreads();

#pragma unroll
    for (int mi = 0; mi < 2; mi++) {
#pragma unroll
        for (int rr = 0; rr < 2; rr++) {
            int rl = mbase + mi * 16 + g + rr * 8;
            int rg = row0 + rl;
            float mean = rmean[rl], istd = rstd[rl];
#pragma unroll
            for (int ni = 0; ni < 4; ni++) {
                int c = nbase + ni * 8 + tg * 2;
                float v0 = (acc[mi][ni][rr * 2 + 0] - mean) * istd * gamma[c] + beta[c];
                float v1 = (acc[mi][ni][rr * 2 + 1] - mean) * istd * gamma[c + 1] + beta[c + 1];
                *reinterpret_cast<float2*>(&out[(long)rg * DDIM + c]) =
                    make_float2(v0, v1);
            }
        }
    }
}

// ---------------- CSR build --------------------------------------------------
__global__ void hist_kernel(const int* __restrict__ dst) {
    int e = blockIdx.x * blockDim.x + threadIdx.x;
    if (e < EE) atomicAdd(&g_cnt[dst[e]], 1);
}

__global__ void scan_kernel() {
    int t = threadIdx.x;
    int lane = t & 31, w = t >> 5;
    int local[16];
    const int4* cp = reinterpret_cast<const int4*>(g_cnt);
#pragma unroll
    for (int i = 0; i < 4; i++) {
        int4 v = cp[t * 4 + i];
        local[i * 4 + 0] = v.x; local[i * 4 + 1] = v.y;
        local[i * 4 + 2] = v.z; local[i * 4 + 3] = v.w;
    }
    int mine = 0;
#pragma unroll
    for (int j = 0; j < 16; j++) mine += local[j];

    int inc = mine;
#pragma unroll
    for (int o = 1; o < 32; o <<= 1) {
        int v = __shfl_up_sync(0xffffffffu, inc, o);
        if (lane >= o) inc += v;
    }
    __shared__ int ws[32];
    if (lane == 31) ws[w] = inc;
    __syncthreads();
    if (w == 0) {
        int v = ws[lane];
#pragma unroll
        for (int o = 1; o < 32; o <<= 1) {
            int u = __shfl_up_sync(0xffffffffu, v, o);
            if (lane >= o) v += u;
        }
        ws[lane] = v;
    }
    __syncthreads();
    int base = ((w > 0) ? ws[w - 1] : 0) + inc - mine;

    int vals[16];
#pragma unroll
    for (int j = 0; j < 16; j++) { vals[j] = base; base += local[j]; }
    int4* op = reinterpret_cast<int4*>(g_off);
    int4* up = reinterpret_cast<int4*>(g_cursor);
#pragma unroll
    for (int i = 0; i < 4; i++) {
        int4 v = make_int4(vals[i * 4], vals[i * 4 + 1], vals[i * 4 + 2], vals[i * 4 + 3]);
        op[t * 4 + i] = v;
        up[t * 4 + i] = v;
    }
    if (t == 1023) g_off[NN] = base;
}

__global__ void scatter_kernel(const int* __restrict__ src,
                               const int* __restrict__ dst) {
    int e = blockIdx.x * blockDim.x + threadIdx.x;
    if (e < EE) {
        int p = atomicAdd(&g_cursor[dst[e]], 1);
        g_esrc[p] = src[e];
    }
}

// ---------------- edge softmax: warp=head, per-head attn planes -------------
__global__ void edge_softmax_kernel() {
    int node = blockIdx.x;
    int w = threadIdx.x >> 5;
    int lane = threadIdx.x & 31;
    int start = g_off[node], end = g_off[node + 1];
    if (start == end) return;
    int dm = g_mask[node];
    int grp = lane >> 3;
    int sub = lane & 7;
    float* __restrict__ ah = g_attn[w];

    const uint2 qu = *reinterpret_cast<const uint2*>(
        &g_qb[(long)node * 128 + w * 16 + sub * 2]);
    float2 q01 = __bfloat1622float2(*reinterpret_cast<const __nv_bfloat162*>(&qu.x));
    float2 q23 = __bfloat1622float2(*reinterpret_cast<const __nv_bfloat162*>(&qu.y));

    float mx = -1e30f;
    for (int p0 = start; p0 < end; p0 += 4) {
        int p = p0 + grp;
        bool valid = (p < end);
        int s = valid ? g_esrc[p] : 0;
        uint2 ku = valid ? *reinterpret_cast<const uint2*>(
                               &g_kb[(long)s * 128 + w * 16 + sub * 2])
                         : make_uint2(0u, 0u);
        float2 k01 = __bfloat1622float2(*reinterpret_cast<const __nv_bfloat162*>(&ku.x));
        float2 k23 = __bfloat1622float2(*reinterpret_cast<const __nv_bfloat162*>(&ku.y));
        float d = q01.x * k01.x + q01.y * k01.y + q23.x * k23.x + q23.y * k23.y;
        d += __shfl_xor_sync(0xffffffffu, d, 1);
        d += __shfl_xor_sync(0xffffffffu, d, 2);
        d += __shfl_xor_sync(0xffffffffu, d, 4);
        if (valid) {
            int m = dm & g_mask[s];
            float sc = m ? d : -10000.0f;
            mx = fmaxf(mx, sc);
            if (sub == 0) ah[p] = sc;
        }
    }
    mx = fmaxf(mx, __shfl_xor_sync(0xffffffffu, mx, 8));
    mx = fmaxf(mx, __shfl_xor_sync(0xffffffffu, mx, 16));
    mx = fmaxf(mx, __shfl_xor_sync(0xffffffffu, mx, 1));
    mx = fmaxf(mx, __shfl_xor_sync(0xffffffffu, mx, 2));
    mx = fmaxf(mx, __shfl_xor_sync(0xffffffffu, mx, 4));
    __syncwarp();

    float den = 0.f;
    for (int p = start + lane; p < end; p += 32) {
        den += expf(ah[p] - mx);
    }
#pragma unroll
    for (int o = 16; o > 0; o >>= 1) den += __shfl_xor_sync(0xffffffffu, den, o);
    float inv = 1.0f / den;
    __syncwarp();
    for (int p = start + lane; p < end; p += 32) {
        ah[p] = expf(ah[p] - mx) * inv;
    }
}

// ---------------- diffusion: h[ii+1] = A_hat @ h[ii] -------------------------
__global__ void diffuse_kernel(int ii, int last) {
    const __nv_bfloat162* __restrict__ hp = g_hb[ii];
    __nv_bfloat162* __restrict__ hn = g_hb[last ? 0 : (ii + 1)];
    int node = blockIdx.x;
    int t = threadIdx.x;
    const float* __restrict__ ah = g_attn[t >> 4];
    int start = g_off[node], end = g_off[node + 1];
    float ax = 0.f, ay = 0.f;
    int p = start;
    for (; p + 8 <= end; p += 8) {
        int s[8]; float a[8]; float2 v[8];
#pragma unroll
        for (int i = 0; i < 8; i++) s[i] = g_esrc[p + i];
#pragma unroll
        for (int i = 0; i < 8; i++) a[i] = ah[p + i];
#pragma unroll
        for (int i = 0; i < 8; i++) v[i] = __bfloat1622float2(hp[(long)s[i] * 128 + t]);
#pragma unroll
        for (int i = 0; i < 8; i++) { ax += a[i] * v[i].x; ay += a[i] * v[i].y; }
    }
    for (; p + 4 <= end; p += 4) {
        int s[4]; float a[4]; float2 v[4];
#pragma unroll
        for (int i = 0; i < 4; i++) s[i] = g_esrc[p + i];
#pragma unroll
        for (int i = 0; i < 4; i++) a[i] = ah[p + i];
#pragma unroll
        for (int i = 0; i < 4; i++) v[i] = __bfloat1622float2(hp[(long)s[i] * 128 + t]);
#pragma unroll
        for (int i = 0; i < 4; i++) { ax += a[i] * v[i].x; ay += a[i] * v[i].y; }
    }
    for (; p < end; p++) {
        int s = g_esrc[p];
        float a = ah[p];
        float2 v = __bfloat1622float2(hp[(long)s * 128 + t]);
        ax += a * v.x;
        ay += a * v.y;
    }
    if (!last) {
        hn[(long)node * 128 + t] = __floats2bfloat162_rn(ax, ay);
    } else {
        float2 h0v = __bfloat1622float2(g_hb[0][(long)node * 128 + t]);
        float2 h1v = __bfloat1622float2(g_hb[1][(long)node * 128 + t]);
        float2 h2v = __bfloat1622float2(g_hb[2][(long)node * 128 + t]);
        const float w3 = 1.0f / 6.0f;
        float gx = h0v.x + h1v.x + 0.5f * h2v.x + w3 * ax;
        float gy = h0v.y + h1v.y + 0.5f * h2v.y + w3 * ay;
        g_gatherb[(long)node * 128 + t] = __floats2bfloat162_rn(gx, gy);
    }
}

// ---------------- launch ------------------------------------------------------
extern "C" void kernel_launch(void* const* d_in, const int* in_sizes, int n_in,
                              void* d_out, int out_size) {
    const void* p4194304 = 0; const void* p16384 = 0;
    const void* p262144a = 0; const void* p262144b = 0;
    const void* p196608 = 0;  const void* p768 = 0; const void* p65536 = 0;
    const void* p256a = 0; const void* p256b = 0; const void* p256c = 0;
    for (int i = 0; i < n_in; i++) {
        int sz = in_sizes[i]; const void* p = d_in[i];
        if      (sz == 4194304) p4194304 = p;
        else if (sz == 16384)   p16384 = p;
        else if (sz == 262144)  { if (!p262144a) p262144a = p; else p262144b = p; }
        else if (sz == 196608)  p196608 = p;
        else if (sz == 768)     p768 = p;
        else if (sz == 65536)   p65536 = p;
        else if (sz == 256)     { if (!p256a) p256a = p; else if (!p256b) p256b = p; else p256c = p; }
    }
    const float* hidden = (const float*)p4194304;
    const float* amask  = (const float*)p16384;
    const int*   src    = (const int*)p262144a;
    const int*   dst    = (const int*)p262144b;
    const float* Wqkv   = (const float*)p196608;
    const float* bqkv   = (const float*)p768;
    const float* Wo     = (const float*)p65536;
    const float* v256_0 = (const float*)p256a;
    const float* v256_1 = (const float*)p256b;
    const float* v256_2 = (const float*)p256c;

    float* out = (float*)d_out;

    static cudaStream_t s2 = nullptr;
    static cudaEvent_t ev_fork = nullptr, ev_join = nullptr;
    if (!s2) {
        cudaStreamCreateWithFlags(&s2, cudaStreamNonBlocking);
        cudaEventCreateWithFlags(&ev_fork, cudaEventDisableTiming);
        cudaEventCreateWithFlags(&ev_join, cudaEventDisableTiming);
    }

    cudaEventRecord(ev_fork, 0);
    cudaStreamWaitEvent(s2, ev_fork, 0);

    prep_kernel<<<NN / 256, 256, 0, s2>>>(amask);
    hist_kernel<<<EE / 256, 256, 0, s2>>>(dst);
    scan_kernel<<<1, 1024, 0, s2>>>();
    scatter_kernel<<<EE / 256, 256, 0, s2>>>(src, dst);
    cudaEventRecord(ev_join, s2);

    setup_kernel<<<8192, 256>>>(hidden, Wqkv, Wo, v256_0, v256_1, v256_2);
    {
        dim3 grid(768 / 64, NN / 128);
        gemm_qkv_kernel<<<grid, 256>>>(bqkv);
    }

    cudaStreamWaitEvent(0, ev_join, 0);

    edge_softmax_kernel<<<NN, 256>>>();

    diffuse_kernel<<<NN, 128>>>(0, 0);
    diffuse_kernel<<<NN, 128>>>(1, 0);
    diffuse_kernel<<<NN, 128>>>(2, 1);

    gemm_ln_kernel<<<NN / 64, 512>>>(hidden, v256_0, v256_1, v256_2, out);
}